// round 7
// baseline (speedup 1.0000x reference)
#include <cuda_runtime.h>

// Problem constants (from reference setup_inputs)
#define B_   256
#define J_   17
#define HW_  6912            // 96*72
#define V4_  (HW_ / 4)       // 1728 float4 per (b,j) slice
#define BJ_  (B_ * J_)       // 4352

// Scratch: transposed partials, g_partials[j * B_ + b] (contiguous per joint)
__device__ float        g_partials[BJ_];
__device__ unsigned int g_done = 0;    // reset by finisher each run

// ---------------------------------------------------------------------------
// Single fused kernel. One block per (b,j) slice. Block 0 additionally acts
// as the finisher: it spins (acquire) on g_done, then reduces + top-k.
// Per-block sync cost is ONE fire-and-forget red.release (no MEMBAR drain,
// no returning atomic) -- this is what R2's fusion got wrong.
// ---------------------------------------------------------------------------
__global__ __launch_bounds__(256) void jmse_fused_kernel(
    const float* __restrict__ out,
    const float* __restrict__ tgt,
    const float* __restrict__ wgt,
    const int*  __restrict__ topk_ptr,
    float*      __restrict__ result)
{
    const int bj = blockIdx.x;
    const int lane = threadIdx.x & 31;
    const int wid  = threadIdx.x >> 5;

    // ---- streaming phase (identical to the proven ~37us loop) ----
    const size_t base = (size_t)bj * HW_;
    const float4* __restrict__ o4 = (const float4*)(out + base);
    const float4* __restrict__ t4 = (const float4*)(tgt + base);

    float acc = 0.0f;
    #pragma unroll 4
    for (int i = threadIdx.x; i < V4_; i += 256) {
        float4 a = o4[i];
        float4 b = t4[i];
        float d0 = a.x - b.x;
        float d1 = a.y - b.y;
        float d2 = a.z - b.z;
        float d3 = a.w - b.w;
        acc = fmaf(d0, d0, acc);
        acc = fmaf(d1, d1, acc);
        acc = fmaf(d2, d2, acc);
        acc = fmaf(d3, d3, acc);
    }

    #pragma unroll
    for (int off = 16; off > 0; off >>= 1)
        acc += __shfl_xor_sync(0xFFFFFFFFu, acc, off);

    __shared__ float warp_sums[8];
    if (lane == 0) warp_sums[wid] = acc;
    __syncthreads();

    if (threadIdx.x == 0) {
        float s = 0.0f;
        #pragma unroll
        for (int w8 = 0; w8 < 8; w8++) s += warp_sums[w8];
        const float w = wgt[bj];                 // [B, J, 1] contiguous
        const int b = bj / J_;
        const int j = bj - b * J_;
        g_partials[j * B_ + b] = s * w * w;      // transposed store
        // Fire-and-forget release increment: orders the store above,
        // costs no MEMBAR drain and returns nothing.
        asm volatile("red.release.gpu.global.add.u32 [%0], 1;"
                     :: "l"(&g_done) : "memory");
    }

    if (blockIdx.x != 0) return;

    // ---- finisher (block 0 only) ----
    if (threadIdx.x == 0) {
        unsigned int v;
        do {
            asm volatile("ld.acquire.gpu.global.u32 %0, [%1];"
                         : "=r"(v) : "l"(&g_done));
            if (v < (unsigned)BJ_) __nanosleep(200);
        } while (v < (unsigned)BJ_);
    }
    __syncthreads();   // broadcast "all partials visible" to the block

    // 8 warps; warp w reduces joints w, w+8, w+16 (contiguous float4 loads)
    __shared__ float losses[J_];
    for (int j = wid; j < J_; j += 8) {
        const float4* p4 = (const float4*)&g_partials[j * B_];
        // __ldcg: read from L2 (bypass possibly-stale L1)
        float4 a = __ldcg(p4 + lane);
        float4 b = __ldcg(p4 + lane + 32);
        float s = (a.x + a.y) + (a.z + a.w) + (b.x + b.y) + (b.z + b.w);
        #pragma unroll
        for (int off = 16; off > 0; off >>= 1)
            s += __shfl_xor_sync(0xFFFFFFFFu, s, off);
        if (lane == 0)
            losses[j] = s * (1.0f / ((float)B_ * (float)HW_));
    }
    __syncthreads();

    if (threadIdx.x == 0) {
        const int k = *topk_ptr;
        float v[J_];
        #pragma unroll
        for (int j = 0; j < J_; j++) v[j] = losses[j];
        float sum = 0.0f;
        for (int s = 0; s < k; s++) {
            int   best_i = 0;
            float best_v = v[0];
            #pragma unroll
            for (int j = 1; j < J_; j++)
                if (v[j] > best_v) { best_v = v[j]; best_i = j; }
            sum += best_v;
            v[best_i] = -3.402823466e38f;
        }
        result[0] = sum / (float)k;
        g_done = 0;   // reset for next graph replay (same thread, after reads)
    }
}

// ---------------------------------------------------------------------------
extern "C" void kernel_launch(void* const* d_in, const int* in_sizes, int n_in,
                              void* d_out, int out_size)
{
    const float* out_t = (const float*)d_in[0];
    const float* tgt_t = (const float*)d_in[1];
    const float* wgt_t = (const float*)d_in[2];
    const int*   topk  = (const int*)d_in[3];
    float* res = (float*)d_out;

    jmse_fused_kernel<<<BJ_, 256>>>(out_t, tgt_t, wgt_t, topk, res);
}